// round 2
// baseline (speedup 1.0000x reference)
#include <cuda_runtime.h>
#include <cstdint>

// Problem constants
#define TQ 4096   // tokens
#define HD 1024   // hidden
#define FD 2048   // ffn dim (w1 rows: [gate(0..FD), up(FD..2FD)])
#define NE 8      // experts
#define NK 2      // top-k

// ---------------------------------------------------------------------------
// Scratch (device globals; runtime allocation is forbidden)
// ---------------------------------------------------------------------------
__device__ int   g_counts[NE];
__device__ int   g_tok[NE * TQ];               // packed t*2+k per expert slot
__device__ float g_wt[TQ * NK];                // combine weight per assignment
__device__ float g_act[(size_t)TQ * NK * FD];  // silu(gate)*up rows  (67 MB)
__device__ float g_y[(size_t)TQ * NK * HD];    // weighted expert outputs (33 MB)

// ---------------------------------------------------------------------------
// Helpers
// ---------------------------------------------------------------------------
// fp32 -> tf32 round-to-nearest. Raw truncation inside the MMA would bias the
// result ~-1e-3 relative; RNA keeps error unbiased (~5e-4 end to end).
__device__ __forceinline__ uint32_t f2tf(float x) {
    uint32_t r;
    asm("cvt.rna.tf32.f32 %0, %1;" : "=r"(r) : "f"(x));
    return r;
}

__device__ __forceinline__ void mma_tf32(float* c, uint32_t a0, uint32_t a1,
                                         uint32_t a2, uint32_t a3,
                                         uint32_t b0, uint32_t b1) {
    asm volatile(
        "mma.sync.aligned.m16n8k8.row.col.f32.tf32.tf32.f32 "
        "{%0,%1,%2,%3}, {%4,%5,%6,%7}, {%8,%9}, {%0,%1,%2,%3};"
        : "+f"(c[0]), "+f"(c[1]), "+f"(c[2]), "+f"(c[3])
        : "r"(a0), "r"(a1), "r"(a2), "r"(a3), "r"(b0), "r"(b1));
}

__device__ __forceinline__ float silu(float x) {
    return x / (1.0f + __expf(-x));
}

// smem row stride (floats). 36 => fragment LDS bank = (4*group + tig) mod 32,
// a bijection over the warp: conflict-free.
#define SSTR 36

// ---------------------------------------------------------------------------
// Kernel 0: zero per-expert counts
// ---------------------------------------------------------------------------
__global__ void k_zero() {
    if (threadIdx.x < NE) g_counts[threadIdx.x] = 0;
}

// ---------------------------------------------------------------------------
// Kernel 1: router. One warp per token.
// ---------------------------------------------------------------------------
__global__ __launch_bounds__(256) void k_router(const float* __restrict__ hs,
                                                const float* __restrict__ gw,
                                                float* __restrict__ logits_out) {
    __shared__ float sg[NE * HD];
    int tid = threadIdx.x;
    for (int i = tid; i < NE * HD; i += 256) sg[i] = gw[i];
    __syncthreads();

    int warp = tid >> 5, lane = tid & 31;
    int t = blockIdx.x * 8 + warp;
    const float* x = hs + (size_t)t * HD;

    float acc[NE];
#pragma unroll
    for (int e = 0; e < NE; e++) acc[e] = 0.f;
    for (int j = lane; j < HD; j += 32) {
        float xv = x[j];
#pragma unroll
        for (int e = 0; e < NE; e++) acc[e] += xv * sg[e * HD + j];
    }
#pragma unroll
    for (int e = 0; e < NE; e++) {
#pragma unroll
        for (int off = 16; off; off >>= 1)
            acc[e] += __shfl_xor_sync(0xffffffffu, acc[e], off);
    }

    if (lane == 0) {
        if (logits_out) {
#pragma unroll
            for (int e = 0; e < NE; e++) logits_out[(size_t)t * NE + e] = acc[e];
        }
        // top-2 (lowest index wins ties, matching lax.top_k)
        float m1 = acc[0]; int i0 = 0;
#pragma unroll
        for (int e = 1; e < NE; e++) if (acc[e] > m1) { m1 = acc[e]; i0 = e; }
        float m2 = -3.4e38f; int i1 = 0;
#pragma unroll
        for (int e = 0; e < NE; e++)
            if (e != i0 && acc[e] > m2) { m2 = acc[e]; i1 = e; }
        // renormalized top-2 softmax weights reduce to the exp ratio
        float e2v = __expf(m2 - m1);
        float inv = 1.0f / (1.0f + e2v);

        int p0 = atomicAdd(&g_counts[i0], 1);
        g_tok[i0 * TQ + p0] = t * 2;
        g_wt[t * 2] = inv;
        int p1 = atomicAdd(&g_counts[i1], 1);
        g_tok[i1 * TQ + p1] = t * 2 + 1;
        g_wt[t * 2 + 1] = e2v * inv;
    }
}

// ---------------------------------------------------------------------------
// Kernel 2: FFN1 grouped GEMM with fused SiLU*up.
// Block tile: 128 rows x 128 mma cols over K=HD. B smem rows interleave
// gate (even) / up (odd) so each thread's (c0,c1) fragment pair is
// (gate, up) for the same output column -> local SiLU fusion.
// grid = (FD/64 = 32 gate-col chunks, NE*32 m-tiles), 256 threads.
// ---------------------------------------------------------------------------
__global__ __launch_bounds__(256) void k_ffn1(const float* __restrict__ hs,
                                              const float* __restrict__ w1) {
    int e  = blockIdx.y >> 5;
    int mt = blockIdx.y & 31;
    int cnt = g_counts[e];
    int m0 = mt * 128;
    if (m0 >= cnt) return;
    int n0 = blockIdx.x * 64;          // gate column base

    __shared__ uint32_t sA[128 * SSTR];
    __shared__ uint32_t sB[128 * SSTR];
    __shared__ int s_tok[128];

    int tid = threadIdx.x;
    if (tid < 128) {
        int idx = m0 + tid;
        s_tok[tid] = (idx < cnt) ? g_tok[e * TQ + idx] : -1;
    }
    __syncthreads();

    int warp = tid >> 5, lane = tid & 31;
    int wm = warp >> 1, wn = warp & 1;      // 4x2 warp grid, warp tile 32x64
    int g = lane >> 2, tg = lane & 3;

    // loader mapping: 2 threads per tile row, 4 float4 each
    int lrow = tid >> 1;
    int lc4  = (tid & 1) * 4;
    int atok = s_tok[lrow];
    const float* aptr = hs + (size_t)(atok >= 0 ? (atok >> 1) : 0) * HD;
    int wrow = (lrow & 1) ? (FD + n0 + (lrow >> 1)) : (n0 + (lrow >> 1));
    const float* bptr = w1 + ((size_t)e * 2 * FD + wrow) * HD;

    float acc[2][8][4];
#pragma unroll
    for (int mi = 0; mi < 2; mi++)
#pragma unroll
        for (int ni = 0; ni < 8; ni++)
#pragma unroll
            for (int q = 0; q < 4; q++) acc[mi][ni][q] = 0.f;

    float4 ra[4], rb[4];
#pragma unroll
    for (int i = 0; i < 4; i++) {
        ra[i] = (atok >= 0) ? *(const float4*)(aptr + (lc4 + i) * 4)
                            : make_float4(0.f, 0.f, 0.f, 0.f);
        rb[i] = *(const float4*)(bptr + (lc4 + i) * 4);
    }

    for (int kc = 0; kc < HD; kc += 32) {
#pragma unroll
        for (int i = 0; i < 4; i++) {
            uint32_t* dA = &sA[lrow * SSTR + (lc4 + i) * 4];
            dA[0] = f2tf(ra[i].x); dA[1] = f2tf(ra[i].y);
            dA[2] = f2tf(ra[i].z); dA[3] = f2tf(ra[i].w);
            uint32_t* dB = &sB[lrow * SSTR + (lc4 + i) * 4];
            dB[0] = f2tf(rb[i].x); dB[1] = f2tf(rb[i].y);
            dB[2] = f2tf(rb[i].z); dB[3] = f2tf(rb[i].w);
        }
        __syncthreads();

        int kn = kc + 32;
        if (kn < HD) {
#pragma unroll
            for (int i = 0; i < 4; i++) {
                ra[i] = (atok >= 0) ? *(const float4*)(aptr + kn + (lc4 + i) * 4)
                                    : make_float4(0.f, 0.f, 0.f, 0.f);
                rb[i] = *(const float4*)(bptr + kn + (lc4 + i) * 4);
            }
        }

#pragma unroll
        for (int ks = 0; ks < 4; ks++) {
            int kb = ks * 8;
            uint32_t bf[8][2];
#pragma unroll
            for (int ni = 0; ni < 8; ni++) {
                int cb = (wn * 64 + ni * 8 + g) * SSTR + kb + tg;
                bf[ni][0] = sB[cb];
                bf[ni][1] = sB[cb + 4];
            }
#pragma unroll
            for (int mi = 0; mi < 2; mi++) {
                int rbse = (wm * 32 + mi * 16 + g) * SSTR + kb + tg;
                uint32_t a0 = sA[rbse];
                uint32_t a1 = sA[rbse + 8 * SSTR];
                uint32_t a2 = sA[rbse + 4];
                uint32_t a3 = sA[rbse + 8 * SSTR + 4];
#pragma unroll
                for (int ni = 0; ni < 8; ni++)
                    mma_tf32(acc[mi][ni], a0, a1, a2, a3, bf[ni][0], bf[ni][1]);
            }
        }
        __syncthreads();
    }

    // Epilogue: even mma col = gate, odd = up (same logical column).
#pragma unroll
    for (int mi = 0; mi < 2; mi++) {
        int rl0 = wm * 32 + mi * 16 + g;
        int t0 = s_tok[rl0], t1 = s_tok[rl0 + 8];
#pragma unroll
        for (int ni = 0; ni < 8; ni++) {
            int colg = n0 + wn * 32 + ni * 4 + tg;
            float* c = acc[mi][ni];
            if (t0 >= 0) g_act[(size_t)t0 * FD + colg] = silu(c[0]) * c[1];
            if (t1 >= 0) g_act[(size_t)t1 * FD + colg] = silu(c[2]) * c[3];
        }
    }
}

// ---------------------------------------------------------------------------
// Kernel 3: FFN2 grouped GEMM (act @ w2[e]^T), scaled by combine weight.
// grid = (HD/128 = 8 n-chunks, NE*32 m-tiles), 256 threads.
// ---------------------------------------------------------------------------
__global__ __launch_bounds__(256) void k_ffn2(const float* __restrict__ w2) {
    int e  = blockIdx.y >> 5;
    int mt = blockIdx.y & 31;
    int cnt = g_counts[e];
    int m0 = mt * 128;
    if (m0 >= cnt) return;
    int n0 = blockIdx.x * 128;

    __shared__ uint32_t sA[128 * SSTR];
    __shared__ uint32_t sB[128 * SSTR];
    __shared__ int s_tok[128];

    int tid = threadIdx.x;
    if (tid < 128) {
        int idx = m0 + tid;
        s_tok[tid] = (idx < cnt) ? g_tok[e * TQ + idx] : -1;
    }
    __syncthreads();

    int warp = tid >> 5, lane = tid & 31;
    int wm = warp >> 1, wn = warp & 1;
    int g = lane >> 2, tg = lane & 3;

    int lrow = tid >> 1;
    int lc4  = (tid & 1) * 4;
    int atok = s_tok[lrow];
    const float* aptr = g_act + (size_t)(atok >= 0 ? atok : 0) * FD;
    const float* bptr = w2 + ((size_t)e * HD + n0 + lrow) * FD;

    float acc[2][8][4];
#pragma unroll
    for (int mi = 0; mi < 2; mi++)
#pragma unroll
        for (int ni = 0; ni < 8; ni++)
#pragma unroll
            for (int q = 0; q < 4; q++) acc[mi][ni][q] = 0.f;

    float4 ra[4], rb[4];
#pragma unroll
    for (int i = 0; i < 4; i++) {
        ra[i] = (atok >= 0) ? *(const float4*)(aptr + (lc4 + i) * 4)
                            : make_float4(0.f, 0.f, 0.f, 0.f);
        rb[i] = *(const float4*)(bptr + (lc4 + i) * 4);
    }

    for (int kc = 0; kc < FD; kc += 32) {
#pragma unroll
        for (int i = 0; i < 4; i++) {
            uint32_t* dA = &sA[lrow * SSTR + (lc4 + i) * 4];
            dA[0] = f2tf(ra[i].x); dA[1] = f2tf(ra[i].y);
            dA[2] = f2tf(ra[i].z); dA[3] = f2tf(ra[i].w);
            uint32_t* dB = &sB[lrow * SSTR + (lc4 + i) * 4];
            dB[0] = f2tf(rb[i].x); dB[1] = f2tf(rb[i].y);
            dB[2] = f2tf(rb[i].z); dB[3] = f2tf(rb[i].w);
        }
        __syncthreads();

        int kn = kc + 32;
        if (kn < FD) {
#pragma unroll
            for (int i = 0; i < 4; i++) {
                ra[i] = (atok >= 0) ? *(const float4*)(aptr + kn + (lc4 + i) * 4)
                                    : make_float4(0.f, 0.f, 0.f, 0.f);
                rb[i] = *(const float4*)(bptr + kn + (lc4 + i) * 4);
            }
        }

#pragma unroll
        for (int ks = 0; ks < 4; ks++) {
            int kb = ks * 8;
            uint32_t bf[8][2];
#pragma unroll
            for (int ni = 0; ni < 8; ni++) {
                int cb = (wn * 64 + ni * 8 + g) * SSTR + kb + tg;
                bf[ni][0] = sB[cb];
                bf[ni][1] = sB[cb + 4];
            }
#pragma unroll
            for (int mi = 0; mi < 2; mi++) {
                int rbse = (wm * 32 + mi * 16 + g) * SSTR + kb + tg;
                uint32_t a0 = sA[rbse];
                uint32_t a1 = sA[rbse + 8 * SSTR];
                uint32_t a2 = sA[rbse + 4];
                uint32_t a3 = sA[rbse + 8 * SSTR + 4];
#pragma unroll
                for (int ni = 0; ni < 8; ni++)
                    mma_tf32(acc[mi][ni], a0, a1, a2, a3, bf[ni][0], bf[ni][1]);
            }
        }
        __syncthreads();
    }

#pragma unroll
    for (int mi = 0; mi < 2; mi++) {
        int rl0 = wm * 32 + mi * 16 + g;
        int t0 = s_tok[rl0], t1 = s_tok[rl0 + 8];
        float w0 = (t0 >= 0) ? g_wt[t0] : 0.f;
        float w1v = (t1 >= 0) ? g_wt[t1] : 0.f;
#pragma unroll
        for (int ni = 0; ni < 8; ni++) {
            int col = n0 + wn * 64 + ni * 8 + tg * 2;
            float* c = acc[mi][ni];
            if (t0 >= 0)
                *(float2*)(g_y + (size_t)t0 * HD + col) =
                    make_float2(w0 * c[0], w0 * c[1]);
            if (t1 >= 0)
                *(float2*)(g_y + (size_t)t1 * HD + col) =
                    make_float2(w1v * c[2], w1v * c[3]);
        }
    }
}

// ---------------------------------------------------------------------------
// Kernel 4: combine the two expert contributions per token (full overwrite).
// ---------------------------------------------------------------------------
__global__ __launch_bounds__(256) void k_combine(float* __restrict__ out) {
    int i = blockIdx.x * 256 + threadIdx.x;   // float4 index over TQ*HD/4
    int t = i >> 8;                           // HD/4 = 256 float4s per token
    int c = i & 255;
    float4 a = ((const float4*)(g_y + (size_t)(2 * t) * HD))[c];
    float4 b = ((const float4*)(g_y + (size_t)(2 * t + 1) * HD))[c];
    ((float4*)out)[i] = make_float4(a.x + b.x, a.y + b.y, a.z + b.z, a.w + b.w);
}

// ---------------------------------------------------------------------------
// Launch
// ---------------------------------------------------------------------------
extern "C" void kernel_launch(void* const* d_in, const int* in_sizes, int n_in,
                              void* d_out, int out_size) {
    const float* hs = (const float*)d_in[0];
    const float* gw = (const float*)d_in[1];
    const float* w1 = (const float*)d_in[2];
    const float* w2 = (const float*)d_in[3];
    float* out = (float*)d_out;
    float* logits = (out_size >= TQ * HD + TQ * NE) ? out + (size_t)TQ * HD
                                                    : nullptr;

    k_zero<<<1, 32>>>();
    k_router<<<TQ / 8, 256>>>(hs, gw, logits);
    k_ffn1<<<dim3(FD / 64, NE * 32), 256>>>(hs, w1);
    k_ffn2<<<dim3(HD / 128, NE * 32), 256>>>(w2);
    k_combine<<<(TQ * HD / 4) / 256, 256>>>(out);
}

// round 3
// speedup vs baseline: 1.3282x; 1.3282x over previous
#include <cuda_runtime.h>
#include <cstdint>

// Problem constants
#define TQ 4096   // tokens
#define HD 1024   // hidden
#define FD 2048   // ffn dim (w1 rows: [gate(0..FD), up(FD..2FD)])
#define NE 8      // experts
#define NK 2      // top-k

// ---------------------------------------------------------------------------
// Scratch (device globals; runtime allocation is forbidden)
// ---------------------------------------------------------------------------
__device__ int   g_counts[NE];
__device__ int   g_tok[NE * TQ];
__device__ float g_wt[TQ * NK];
__device__ float g_act[(size_t)TQ * NK * FD];        // tf32-rounded silu(g)*u
__device__ float g_y[(size_t)TQ * NK * HD];
__device__ float g_hst[(size_t)TQ * HD];             // tf32-rounded hs
__device__ float g_w1t[(size_t)NE * 2 * FD * HD];    // tf32-rounded w1 (134MB)
__device__ float g_w2t[(size_t)NE * HD * FD];        // tf32-rounded w2 (67MB)

// ---------------------------------------------------------------------------
// Helpers
// ---------------------------------------------------------------------------
__device__ __forceinline__ uint32_t f2tf(float x) {
    uint32_t r;
    asm("cvt.rna.tf32.f32 %0, %1;" : "=r"(r) : "f"(x));
    return r;
}
__device__ __forceinline__ uint32_t s2u(const void* p) {
    uint32_t a;
    asm("{ .reg .u64 t; cvta.to.shared.u64 t, %1; cvt.u32.u64 %0, t; }"
        : "=r"(a) : "l"(p));
    return a;
}
__device__ __forceinline__ void mma_tf32(float* c, uint32_t a0, uint32_t a1,
                                         uint32_t a2, uint32_t a3,
                                         uint32_t b0, uint32_t b1) {
    asm volatile(
        "mma.sync.aligned.m16n8k8.row.col.f32.tf32.tf32.f32 "
        "{%0,%1,%2,%3}, {%4,%5,%6,%7}, {%8,%9}, {%0,%1,%2,%3};"
        : "+f"(c[0]), "+f"(c[1]), "+f"(c[2]), "+f"(c[3])
        : "r"(a0), "r"(a1), "r"(a2), "r"(a3), "r"(b0), "r"(b1));
}
__device__ __forceinline__ float silu(float x) {
    return x / (1.0f + __expf(-x));
}

// 16B cp.async with zero-fill when sz==0 (invalid A rows)
#define CPA16(sa, ga, sz)                                                      \
    asm volatile("cp.async.cg.shared.global [%0], [%1], 16, %2;"               \
                 :: "r"(sa), "l"(ga), "r"(sz) : "memory")

// Load one 128x32 A tile + 128x32 B tile into stage ST (32KB/stage), swizzled:
// physical 16B-chunk = chunk ^ (row & 7). Commits one cp.async group.
#define LOAD_STAGE(KC, ST) do {                                                \
    uint32_t _b = sbase + (uint32_t)(ST) * 32768u;                             \
    const float* _a = aptr + (KC);                                             \
    const float* _w = bptr + (KC);                                             \
    _Pragma("unroll")                                                          \
    for (int _c = 0; _c < 4; _c++) {                                           \
        CPA16(_b + offs[_c], _a + _c * 4, za);                                 \
        CPA16(_b + 16384u + offs[_c], _w + _c * 4, 16u);                       \
    }                                                                          \
    asm volatile("cp.async.commit_group;" ::: "memory");                       \
} while (0)

// ---------------------------------------------------------------------------
// Kernel 0: zero per-expert counts
// ---------------------------------------------------------------------------
__global__ void k_zero() {
    if (threadIdx.x < NE) g_counts[threadIdx.x] = 0;
}

// ---------------------------------------------------------------------------
// Kernel 0b: tf32-round a tensor into scratch (float4 grid-stride-free)
// ---------------------------------------------------------------------------
__global__ __launch_bounds__(256) void k_cvt(const float4* __restrict__ src,
                                             float4* __restrict__ dst, int n4) {
    int i = blockIdx.x * 256 + threadIdx.x;
    if (i >= n4) return;
    float4 v = src[i];
    float4 o;
    o.x = __uint_as_float(f2tf(v.x));
    o.y = __uint_as_float(f2tf(v.y));
    o.z = __uint_as_float(f2tf(v.z));
    o.w = __uint_as_float(f2tf(v.w));
    dst[i] = o;
}

// ---------------------------------------------------------------------------
// Kernel 1: router. One warp per token.
// ---------------------------------------------------------------------------
__global__ __launch_bounds__(256) void k_router(const float* __restrict__ hs,
                                                const float* __restrict__ gw,
                                                float* __restrict__ logits_out) {
    __shared__ float sg[NE * HD];
    int tid = threadIdx.x;
    for (int i = tid; i < NE * HD; i += 256) sg[i] = gw[i];
    __syncthreads();

    int warp = tid >> 5, lane = tid & 31;
    int t = blockIdx.x * 8 + warp;
    const float* x = hs + (size_t)t * HD;

    float acc[NE];
#pragma unroll
    for (int e = 0; e < NE; e++) acc[e] = 0.f;
    for (int j = lane; j < HD; j += 32) {
        float xv = x[j];
#pragma unroll
        for (int e = 0; e < NE; e++) acc[e] += xv * sg[e * HD + j];
    }
#pragma unroll
    for (int e = 0; e < NE; e++) {
#pragma unroll
        for (int off = 16; off; off >>= 1)
            acc[e] += __shfl_xor_sync(0xffffffffu, acc[e], off);
    }

    if (lane == 0) {
        if (logits_out) {
#pragma unroll
            for (int e = 0; e < NE; e++) logits_out[(size_t)t * NE + e] = acc[e];
        }
        float m1 = acc[0]; int i0 = 0;
#pragma unroll
        for (int e = 1; e < NE; e++) if (acc[e] > m1) { m1 = acc[e]; i0 = e; }
        float m2 = -3.4e38f; int i1 = 0;
#pragma unroll
        for (int e = 0; e < NE; e++)
            if (e != i0 && acc[e] > m2) { m2 = acc[e]; i1 = e; }
        float e2v = __expf(m2 - m1);
        float inv = 1.0f / (1.0f + e2v);

        int p0 = atomicAdd(&g_counts[i0], 1);
        g_tok[i0 * TQ + p0] = t * 2;
        g_wt[t * 2] = inv;
        int p1 = atomicAdd(&g_counts[i1], 1);
        g_tok[i1 * TQ + p1] = t * 2 + 1;
        g_wt[t * 2 + 1] = e2v * inv;
    }
}

// ---------------------------------------------------------------------------
// Kernel 2: FFN1 grouped GEMM with fused SiLU*up.
// 128 rows x 128 mma cols (64 gate cols interleaved with 64 up cols).
// 3-stage cp.async pipeline, 1 syncthreads/K-chunk, 2 CTAs/SM.
// grid = (FD/64 = 32, NE*32), 256 threads.
// ---------------------------------------------------------------------------
__global__ __launch_bounds__(256, 2) void k_ffn1() {
    int e  = blockIdx.y >> 5;
    int mt = blockIdx.y & 31;
    int cnt = g_counts[e];
    int m0 = mt * 128;
    if (m0 >= cnt) return;
    int n0 = blockIdx.x * 64;

    extern __shared__ char dsm[];
    __shared__ int s_tok[128];

    int tid = threadIdx.x;
    if (tid < 128) {
        int idx = m0 + tid;
        s_tok[tid] = (idx < cnt) ? g_tok[e * TQ + idx] : -1;
    }
    __syncthreads();

    int warp = tid >> 5, lane = tid & 31;
    int wm = warp >> 1, wn = warp & 1;      // 4x2 warps, warp tile 32x64
    int g = lane >> 2, tg = lane & 3;

    // loader: 2 threads per tile row, 4 x 16B chunks each
    int lrow = tid >> 1, lcb = (tid & 1) * 4;
    int atok = s_tok[lrow];
    uint32_t za = (atok >= 0) ? 16u : 0u;
    const float* aptr = g_hst + (size_t)(atok >= 0 ? (atok >> 1) : 0) * HD + lcb * 4;
    int wrow = (lrow & 1) ? (FD + n0 + (lrow >> 1)) : (n0 + (lrow >> 1));
    const float* bptr = g_w1t + ((size_t)e * 2 * FD + wrow) * HD + lcb * 4;

    uint32_t sbase = s2u(dsm);
    uint32_t offs[4];
#pragma unroll
    for (int c = 0; c < 4; c++)
        offs[c] = (uint32_t)((lrow * 32 + (((lcb + c) ^ (lrow & 7)) << 2)) * 4);

    float acc[2][8][4];
#pragma unroll
    for (int mi = 0; mi < 2; mi++)
#pragma unroll
        for (int ni = 0; ni < 8; ni++)
#pragma unroll
            for (int q = 0; q < 4; q++) acc[mi][ni][q] = 0.f;

    const int NKC = HD / 32;   // 32
    LOAD_STAGE(0, 0);
    LOAD_STAGE(32, 1);

    for (int i = 0; i < NKC; i++) {
        asm volatile("cp.async.wait_group 1;" ::: "memory");
        __syncthreads();
        if (i + 2 < NKC) {
            int st = (i + 2) % 3;
            LOAD_STAGE((i + 2) * 32, st);
        } else {
            asm volatile("cp.async.commit_group;" ::: "memory");
        }

        const uint32_t* sA = (const uint32_t*)(dsm + (size_t)(i % 3) * 32768);
        const uint32_t* sB = sA + 4096;
#pragma unroll
        for (int ks = 0; ks < 4; ks++) {
            int x0 = ((2 * ks) ^ g) << 2;
            int x1 = ((2 * ks + 1) ^ g) << 2;
            uint32_t bf[8][2];
#pragma unroll
            for (int ni = 0; ni < 8; ni++) {
                int C = (wn * 64 + ni * 8 + g) * 32;
                bf[ni][0] = sB[C + x0 + tg];
                bf[ni][1] = sB[C + x1 + tg];
            }
#pragma unroll
            for (int mi = 0; mi < 2; mi++) {
                int R = (wm * 32 + mi * 16 + g) * 32;
                uint32_t a0 = sA[R + x0 + tg];
                uint32_t a1 = sA[R + 256 + x0 + tg];
                uint32_t a2 = sA[R + x1 + tg];
                uint32_t a3 = sA[R + 256 + x1 + tg];
#pragma unroll
                for (int ni = 0; ni < 8; ni++)
                    mma_tf32(acc[mi][ni], a0, a1, a2, a3, bf[ni][0], bf[ni][1]);
            }
        }
    }

    // Epilogue: even mma col = gate, odd = up; write tf32-rounded activation.
#pragma unroll
    for (int mi = 0; mi < 2; mi++) {
        int rl0 = wm * 32 + mi * 16 + g;
        int t0 = s_tok[rl0], t1 = s_tok[rl0 + 8];
#pragma unroll
        for (int ni = 0; ni < 8; ni++) {
            int colg = n0 + wn * 32 + ni * 4 + tg;
            float* c = acc[mi][ni];
            if (t0 >= 0)
                g_act[(size_t)t0 * FD + colg] =
                    __uint_as_float(f2tf(silu(c[0]) * c[1]));
            if (t1 >= 0)
                g_act[(size_t)t1 * FD + colg] =
                    __uint_as_float(f2tf(silu(c[2]) * c[3]));
        }
    }
}

// ---------------------------------------------------------------------------
// Kernel 3: FFN2 grouped GEMM (act @ w2[e]^T), scaled by combine weight.
// grid = (HD/128 = 8, NE*32), 256 threads, same pipeline.
// ---------------------------------------------------------------------------
__global__ __launch_bounds__(256, 2) void k_ffn2() {
    int e  = blockIdx.y >> 5;
    int mt = blockIdx.y & 31;
    int cnt = g_counts[e];
    int m0 = mt * 128;
    if (m0 >= cnt) return;
    int n0 = blockIdx.x * 128;

    extern __shared__ char dsm[];
    __shared__ int s_tok[128];

    int tid = threadIdx.x;
    if (tid < 128) {
        int idx = m0 + tid;
        s_tok[tid] = (idx < cnt) ? g_tok[e * TQ + idx] : -1;
    }
    __syncthreads();

    int warp = tid >> 5, lane = tid & 31;
    int wm = warp >> 1, wn = warp & 1;
    int g = lane >> 2, tg = lane & 3;

    int lrow = tid >> 1, lcb = (tid & 1) * 4;
    int atok = s_tok[lrow];
    uint32_t za = (atok >= 0) ? 16u : 0u;
    const float* aptr = g_act + (size_t)(atok >= 0 ? atok : 0) * FD + lcb * 4;
    const float* bptr = g_w2t + ((size_t)e * HD + n0 + lrow) * FD + lcb * 4;

    uint32_t sbase = s2u(dsm);
    uint32_t offs[4];
#pragma unroll
    for (int c = 0; c < 4; c++)
        offs[c] = (uint32_t)((lrow * 32 + (((lcb + c) ^ (lrow & 7)) << 2)) * 4);

    float acc[2][8][4];
#pragma unroll
    for (int mi = 0; mi < 2; mi++)
#pragma unroll
        for (int ni = 0; ni < 8; ni++)
#pragma unroll
            for (int q = 0; q < 4; q++) acc[mi][ni][q] = 0.f;

    const int NKC = FD / 32;   // 64
    LOAD_STAGE(0, 0);
    LOAD_STAGE(32, 1);

    for (int i = 0; i < NKC; i++) {
        asm volatile("cp.async.wait_group 1;" ::: "memory");
        __syncthreads();
        if (i + 2 < NKC) {
            int st = (i + 2) % 3;
            LOAD_STAGE((i + 2) * 32, st);
        } else {
            asm volatile("cp.async.commit_group;" ::: "memory");
        }

        const uint32_t* sA = (const uint32_t*)(dsm + (size_t)(i % 3) * 32768);
        const uint32_t* sB = sA + 4096;
#pragma unroll
        for (int ks = 0; ks < 4; ks++) {
            int x0 = ((2 * ks) ^ g) << 2;
            int x1 = ((2 * ks + 1) ^ g) << 2;
            uint32_t bf[8][2];
#pragma unroll
            for (int ni = 0; ni < 8; ni++) {
                int C = (wn * 64 + ni * 8 + g) * 32;
                bf[ni][0] = sB[C + x0 + tg];
                bf[ni][1] = sB[C + x1 + tg];
            }
#pragma unroll
            for (int mi = 0; mi < 2; mi++) {
                int R = (wm * 32 + mi * 16 + g) * 32;
                uint32_t a0 = sA[R + x0 + tg];
                uint32_t a1 = sA[R + 256 + x0 + tg];
                uint32_t a2 = sA[R + x1 + tg];
                uint32_t a3 = sA[R + 256 + x1 + tg];
#pragma unroll
                for (int ni = 0; ni < 8; ni++)
                    mma_tf32(acc[mi][ni], a0, a1, a2, a3, bf[ni][0], bf[ni][1]);
            }
        }
    }

#pragma unroll
    for (int mi = 0; mi < 2; mi++) {
        int rl0 = wm * 32 + mi * 16 + g;
        int t0 = s_tok[rl0], t1 = s_tok[rl0 + 8];
        float w0 = (t0 >= 0) ? g_wt[t0] : 0.f;
        float w1v = (t1 >= 0) ? g_wt[t1] : 0.f;
#pragma unroll
        for (int ni = 0; ni < 8; ni++) {
            int col = n0 + wn * 64 + ni * 8 + tg * 2;
            float* c = acc[mi][ni];
            if (t0 >= 0)
                *(float2*)(g_y + (size_t)t0 * HD + col) =
                    make_float2(w0 * c[0], w0 * c[1]);
            if (t1 >= 0)
                *(float2*)(g_y + (size_t)t1 * HD + col) =
                    make_float2(w1v * c[2], w1v * c[3]);
        }
    }
}

// ---------------------------------------------------------------------------
// Kernel 4: combine the two expert contributions per token (full overwrite).
// ---------------------------------------------------------------------------
__global__ __launch_bounds__(256) void k_combine(float* __restrict__ out) {
    int i = blockIdx.x * 256 + threadIdx.x;
    int t = i >> 8;
    int c = i & 255;
    float4 a = ((const float4*)(g_y + (size_t)(2 * t) * HD))[c];
    float4 b = ((const float4*)(g_y + (size_t)(2 * t + 1) * HD))[c];
    ((float4*)out)[i] = make_float4(a.x + b.x, a.y + b.y, a.z + b.z, a.w + b.w);
}

// ---------------------------------------------------------------------------
// Launch
// ---------------------------------------------------------------------------
extern "C" void kernel_launch(void* const* d_in, const int* in_sizes, int n_in,
                              void* d_out, int out_size) {
    const float* hs = (const float*)d_in[0];
    const float* gw = (const float*)d_in[1];
    const float* w1 = (const float*)d_in[2];
    const float* w2 = (const float*)d_in[3];
    float* out = (float*)d_out;
    float* logits = (out_size >= TQ * HD + TQ * NE) ? out + (size_t)TQ * HD
                                                    : nullptr;

    static const int DSMEM = 98304;  // 3 stages x (16KB A + 16KB B)
    static bool attr_done = false;
    if (!attr_done) {
        cudaFuncSetAttribute(k_ffn1, cudaFuncAttributeMaxDynamicSharedMemorySize, DSMEM);
        cudaFuncSetAttribute(k_ffn2, cudaFuncAttributeMaxDynamicSharedMemorySize, DSMEM);
        attr_done = true;
    }

    float* w1t; cudaGetSymbolAddress((void**)&w1t, g_w1t);
    float* w2t; cudaGetSymbolAddress((void**)&w2t, g_w2t);
    float* hst; cudaGetSymbolAddress((void**)&hst, g_hst);

    k_zero<<<1, 32>>>();
    k_router<<<TQ / 8, 256>>>(hs, gw, logits);
    k_cvt<<<(NE * 2 * FD * HD / 4) / 256, 256>>>((const float4*)w1, (float4*)w1t,
                                                 NE * 2 * FD * HD / 4);
    k_cvt<<<(NE * HD * FD / 4) / 256, 256>>>((const float4*)w2, (float4*)w2t,
                                             NE * HD * FD / 4);
    k_cvt<<<(TQ * HD / 4) / 256, 256>>>((const float4*)hs, (float4*)hst,
                                        TQ * HD / 4);
    k_ffn1<<<dim3(FD / 64, NE * 32), 256, DSMEM>>>();
    k_ffn2<<<dim3(HD / 128, NE * 32), 256, DSMEM>>>();
    k_combine<<<(TQ * HD / 4) / 256, 256>>>(out);
}

// round 4
// speedup vs baseline: 1.4289x; 1.0758x over previous
#include <cuda_runtime.h>
#include <cstdint>

// Problem constants
#define TQ 4096   // tokens
#define HD 1024   // hidden
#define FD 2048   // ffn dim (w1 rows: [gate(0..FD), up(FD..2FD)])
#define NE 8      // experts
#define NK 2      // top-k

// ---------------------------------------------------------------------------
// Scratch (device globals; runtime allocation is forbidden)
// ---------------------------------------------------------------------------
__device__ int   g_counts[NE];
__device__ int   g_tok[NE * TQ];
__device__ float g_wt[TQ * NK];
__device__ float g_act[(size_t)TQ * NK * FD];        // tf32-rounded silu(g)*u
__device__ float g_y[(size_t)TQ * NK * HD];
__device__ float g_hst[(size_t)TQ * HD];             // tf32-rounded hs
__device__ float g_w1t[(size_t)NE * 2 * FD * HD];    // tf32-rounded w1
__device__ float g_w2t[(size_t)NE * HD * FD];        // tf32-rounded w2

// ---------------------------------------------------------------------------
// Helpers
// ---------------------------------------------------------------------------
__device__ __forceinline__ uint32_t f2tf(float x) {
    uint32_t r;
    asm("cvt.rna.tf32.f32 %0, %1;" : "=r"(r) : "f"(x));
    return r;
}
__device__ __forceinline__ uint32_t s2u(const void* p) {
    uint32_t a;
    asm("{ .reg .u64 t; cvta.to.shared.u64 t, %1; cvt.u32.u64 %0, t; }"
        : "=r"(a) : "l"(p));
    return a;
}
__device__ __forceinline__ void mma_tf32(float* c, const uint32_t* a,
                                         uint32_t b0, uint32_t b1) {
    asm volatile(
        "mma.sync.aligned.m16n8k8.row.col.f32.tf32.tf32.f32 "
        "{%0,%1,%2,%3}, {%4,%5,%6,%7}, {%8,%9}, {%0,%1,%2,%3};"
        : "+f"(c[0]), "+f"(c[1]), "+f"(c[2]), "+f"(c[3])
        : "r"(a[0]), "r"(a[1]), "r"(a[2]), "r"(a[3]), "r"(b0), "r"(b1));
}
// ldmatrix x4 over b16: with 16B rows = 4 tf32, lane receives tf32
// element [lane/4][lane%4] of each 8x4 matrix — exactly the mma frag layout.
__device__ __forceinline__ void ldsm4(uint32_t* r, uint32_t addr) {
    asm volatile("ldmatrix.sync.aligned.m8n8.x4.shared.b16 {%0,%1,%2,%3}, [%4];"
                 : "=r"(r[0]), "=r"(r[1]), "=r"(r[2]), "=r"(r[3]) : "r"(addr));
}
__device__ __forceinline__ float silu(float x) {
    return x / (1.0f + __expf(-x));
}

// 16B cp.async with zero-fill when sz==0 (invalid A rows)
#define CPA16(sa, ga, sz)                                                      \
    asm volatile("cp.async.cg.shared.global [%0], [%1], 16, %2;"               \
                 :: "r"(sa), "l"(ga), "r"(sz) : "memory")

// Load one 128x32 A tile + 128x32 B tile into stage ST (32KB/stage), swizzled:
// physical 16B-chunk = chunk ^ (row & 7). Commits one cp.async group.
#define LOAD_STAGE(KC, ST) do {                                                \
    uint32_t _b = sbase + (uint32_t)(ST) * 32768u;                             \
    const float* _a = aptr + (KC);                                             \
    const float* _w = bptr + (KC);                                             \
    _Pragma("unroll")                                                          \
    for (int _c = 0; _c < 4; _c++) {                                           \
        CPA16(_b + offs[_c], _a + _c * 4, za);                                 \
        CPA16(_b + 16384u + offs[_c], _w + _c * 4, 16u);                       \
    }                                                                          \
    asm volatile("cp.async.commit_group;" ::: "memory");                       \
} while (0)

// Fragment-load + MMA for one K-chunk (shared by both FFN kernels).
// Needs: sbase, stage index IST, per-lane aoffA/aoffB/xa[]/xb[], acc.
#define CHUNK_MMA(IST) do {                                                    \
    uint32_t _sA = sbase + (uint32_t)(IST) * 32768u;                           \
    uint32_t _sB = _sA + 16384u;                                               \
    _Pragma("unroll")                                                          \
    for (int ks = 0; ks < 4; ks++) {                                           \
        uint32_t br[4][4];                                                     \
        _Pragma("unroll")                                                      \
        for (int nip = 0; nip < 4; nip++)                                      \
            ldsm4(br[nip], _sB + aoffB + nip * 2048u + xb[ks]);                \
        uint32_t ar[2][4];                                                     \
        _Pragma("unroll")                                                      \
        for (int mi = 0; mi < 2; mi++)                                         \
            ldsm4(ar[mi], _sA + aoffA + mi * 2048u + xa[ks]);                  \
        _Pragma("unroll")                                                      \
        for (int mi = 0; mi < 2; mi++)                                         \
            _Pragma("unroll")                                                  \
            for (int ni = 0; ni < 8; ni++)                                     \
                mma_tf32(acc[mi][ni], ar[mi],                                  \
                         br[ni >> 1][2 * (ni & 1)],                            \
                         br[ni >> 1][2 * (ni & 1) + 1]);                       \
    }                                                                          \
} while (0)

// ---------------------------------------------------------------------------
// Kernel 0: zero per-expert counts
// ---------------------------------------------------------------------------
__global__ void k_zero() {
    if (threadIdx.x < NE) g_counts[threadIdx.x] = 0;
}

// ---------------------------------------------------------------------------
// Kernel 0b: tf32-round a tensor into scratch
// ---------------------------------------------------------------------------
__global__ __launch_bounds__(256) void k_cvt(const float4* __restrict__ src,
                                             float4* __restrict__ dst, int n4) {
    int i = blockIdx.x * 256 + threadIdx.x;
    if (i >= n4) return;
    float4 v = src[i];
    float4 o;
    o.x = __uint_as_float(f2tf(v.x));
    o.y = __uint_as_float(f2tf(v.y));
    o.z = __uint_as_float(f2tf(v.z));
    o.w = __uint_as_float(f2tf(v.w));
    dst[i] = o;
}

// ---------------------------------------------------------------------------
// Kernel 1: router. One warp per token.
// ---------------------------------------------------------------------------
__global__ __launch_bounds__(256) void k_router(const float* __restrict__ hs,
                                                const float* __restrict__ gw,
                                                float* __restrict__ logits_out) {
    __shared__ float sg[NE * HD];
    int tid = threadIdx.x;
    for (int i = tid; i < NE * HD; i += 256) sg[i] = gw[i];
    __syncthreads();

    int warp = tid >> 5, lane = tid & 31;
    int t = blockIdx.x * 8 + warp;
    const float* x = hs + (size_t)t * HD;

    float acc[NE];
#pragma unroll
    for (int e = 0; e < NE; e++) acc[e] = 0.f;
    for (int j = lane; j < HD; j += 32) {
        float xv = x[j];
#pragma unroll
        for (int e = 0; e < NE; e++) acc[e] += xv * sg[e * HD + j];
    }
#pragma unroll
    for (int e = 0; e < NE; e++) {
#pragma unroll
        for (int off = 16; off; off >>= 1)
            acc[e] += __shfl_xor_sync(0xffffffffu, acc[e], off);
    }

    if (lane == 0) {
        if (logits_out) {
#pragma unroll
            for (int e = 0; e < NE; e++) logits_out[(size_t)t * NE + e] = acc[e];
        }
        float m1 = acc[0]; int i0 = 0;
#pragma unroll
        for (int e = 1; e < NE; e++) if (acc[e] > m1) { m1 = acc[e]; i0 = e; }
        float m2 = -3.4e38f; int i1 = 0;
#pragma unroll
        for (int e = 0; e < NE; e++)
            if (e != i0 && acc[e] > m2) { m2 = acc[e]; i1 = e; }
        float e2v = __expf(m2 - m1);
        float inv = 1.0f / (1.0f + e2v);

        int p0 = atomicAdd(&g_counts[i0], 1);
        g_tok[i0 * TQ + p0] = t * 2;
        g_wt[t * 2] = inv;
        int p1 = atomicAdd(&g_counts[i1], 1);
        g_tok[i1 * TQ + p1] = t * 2 + 1;
        g_wt[t * 2 + 1] = e2v * inv;
    }
}

// ---------------------------------------------------------------------------
// Kernel 2: FFN1 grouped GEMM with fused SiLU*up.
// 128 rows x 128 mma cols (gate/up interleaved). 3-stage cp.async pipeline,
// ldmatrix fragment loads. grid = (FD/64 = 32, NE*32), 256 threads.
// ---------------------------------------------------------------------------
__global__ __launch_bounds__(256, 2) void k_ffn1() {
    int e  = blockIdx.y >> 5;
    int mt = blockIdx.y & 31;
    int cnt = g_counts[e];
    int m0 = mt * 128;
    if (m0 >= cnt) return;
    int n0 = blockIdx.x * 64;

    extern __shared__ char dsm[];
    __shared__ int s_tok[128];

    int tid = threadIdx.x;
    if (tid < 128) {
        int idx = m0 + tid;
        s_tok[tid] = (idx < cnt) ? g_tok[e * TQ + idx] : -1;
    }
    __syncthreads();

    int warp = tid >> 5, lane = tid & 31;
    int wm = warp >> 1, wn = warp & 1;      // 4x2 warps, warp tile 32x64
    int g = lane >> 2, tg = lane & 3;

    // loader: 2 threads per tile row, 4 x 16B chunks each
    int lrow = tid >> 1, lcb = (tid & 1) * 4;
    int atok = s_tok[lrow];
    uint32_t za = (atok >= 0) ? 16u : 0u;
    const float* aptr = g_hst + (size_t)(atok >= 0 ? (atok >> 1) : 0) * HD + lcb * 4;
    int wrow = (lrow & 1) ? (FD + n0 + (lrow >> 1)) : (n0 + (lrow >> 1));
    const float* bptr = g_w1t + ((size_t)e * 2 * FD + wrow) * HD + lcb * 4;

    uint32_t sbase = s2u(dsm);
    uint32_t offs[4];
#pragma unroll
    for (int c = 0; c < 4; c++)
        offs[c] = (uint32_t)((lrow * 32 + (((lcb + c) ^ (lrow & 7)) << 2)) * 4);

    // ldmatrix per-lane address components
    int j = lane >> 3, r = lane & 7;
    uint32_t aoffA = (uint32_t)((wm * 32 + ((j & 1) << 3) + r) * 128);
    uint32_t aoffB = (uint32_t)((wn * 64 + ((j >> 1) << 3) + r) * 128);
    int cjA = j >> 1, cjB = j & 1;
    uint32_t xa[4], xb[4];
#pragma unroll
    for (int ks = 0; ks < 4; ks++) {
        xa[ks] = (uint32_t)((((2 * ks + cjA) ^ r) << 4));
        xb[ks] = (uint32_t)((((2 * ks + cjB) ^ r) << 4));
    }

    float acc[2][8][4];
#pragma unroll
    for (int mi = 0; mi < 2; mi++)
#pragma unroll
        for (int ni = 0; ni < 8; ni++)
#pragma unroll
            for (int q = 0; q < 4; q++) acc[mi][ni][q] = 0.f;

    const int NKC = HD / 32;   // 32
    LOAD_STAGE(0, 0);
    LOAD_STAGE(32, 1);

    for (int i = 0; i < NKC; i++) {
        asm volatile("cp.async.wait_group 1;" ::: "memory");
        __syncthreads();
        if (i + 2 < NKC) {
            int st = (i + 2) % 3;
            LOAD_STAGE((i + 2) * 32, st);
        } else {
            asm volatile("cp.async.commit_group;" ::: "memory");
        }
        CHUNK_MMA(i % 3);
    }

    // Epilogue: even mma col = gate, odd = up; write tf32-rounded activation.
#pragma unroll
    for (int mi = 0; mi < 2; mi++) {
        int rl0 = wm * 32 + mi * 16 + g;
        int t0 = s_tok[rl0], t1 = s_tok[rl0 + 8];
#pragma unroll
        for (int ni = 0; ni < 8; ni++) {
            int colg = n0 + wn * 32 + ni * 4 + tg;
            float* c = acc[mi][ni];
            if (t0 >= 0)
                g_act[(size_t)t0 * FD + colg] =
                    __uint_as_float(f2tf(silu(c[0]) * c[1]));
            if (t1 >= 0)
                g_act[(size_t)t1 * FD + colg] =
                    __uint_as_float(f2tf(silu(c[2]) * c[3]));
        }
    }
}

// ---------------------------------------------------------------------------
// Kernel 3: FFN2 grouped GEMM (act @ w2[e]^T), scaled by combine weight.
// grid = (HD/128 = 8, NE*32), 256 threads, same pipeline.
// ---------------------------------------------------------------------------
__global__ __launch_bounds__(256, 2) void k_ffn2() {
    int e  = blockIdx.y >> 5;
    int mt = blockIdx.y & 31;
    int cnt = g_counts[e];
    int m0 = mt * 128;
    if (m0 >= cnt) return;
    int n0 = blockIdx.x * 128;

    extern __shared__ char dsm[];
    __shared__ int s_tok[128];

    int tid = threadIdx.x;
    if (tid < 128) {
        int idx = m0 + tid;
        s_tok[tid] = (idx < cnt) ? g_tok[e * TQ + idx] : -1;
    }
    __syncthreads();

    int warp = tid >> 5, lane = tid & 31;
    int wm = warp >> 1, wn = warp & 1;
    int g = lane >> 2, tg = lane & 3;

    int lrow = tid >> 1, lcb = (tid & 1) * 4;
    int atok = s_tok[lrow];
    uint32_t za = (atok >= 0) ? 16u : 0u;
    const float* aptr = g_act + (size_t)(atok >= 0 ? atok : 0) * FD + lcb * 4;
    const float* bptr = g_w2t + ((size_t)e * HD + n0 + lrow) * FD + lcb * 4;

    uint32_t sbase = s2u(dsm);
    uint32_t offs[4];
#pragma unroll
    for (int c = 0; c < 4; c++)
        offs[c] = (uint32_t)((lrow * 32 + (((lcb + c) ^ (lrow & 7)) << 2)) * 4);

    int j = lane >> 3, r = lane & 7;
    uint32_t aoffA = (uint32_t)((wm * 32 + ((j & 1) << 3) + r) * 128);
    uint32_t aoffB = (uint32_t)((wn * 64 + ((j >> 1) << 3) + r) * 128);
    int cjA = j >> 1, cjB = j & 1;
    uint32_t xa[4], xb[4];
#pragma unroll
    for (int ks = 0; ks < 4; ks++) {
        xa[ks] = (uint32_t)((((2 * ks + cjA) ^ r) << 4));
        xb[ks] = (uint32_t)((((2 * ks + cjB) ^ r) << 4));
    }

    float acc[2][8][4];
#pragma unroll
    for (int mi = 0; mi < 2; mi++)
#pragma unroll
        for (int ni = 0; ni < 8; ni++)
#pragma unroll
            for (int q = 0; q < 4; q++) acc[mi][ni][q] = 0.f;

    const int NKC = FD / 32;   // 64
    LOAD_STAGE(0, 0);
    LOAD_STAGE(32, 1);

    for (int i = 0; i < NKC; i++) {
        asm volatile("cp.async.wait_group 1;" ::: "memory");
        __syncthreads();
        if (i + 2 < NKC) {
            int st = (i + 2) % 3;
            LOAD_STAGE((i + 2) * 32, st);
        } else {
            asm volatile("cp.async.commit_group;" ::: "memory");
        }
        CHUNK_MMA(i % 3);
    }

#pragma unroll
    for (int mi = 0; mi < 2; mi++) {
        int rl0 = wm * 32 + mi * 16 + g;
        int t0 = s_tok[rl0], t1 = s_tok[rl0 + 8];
        float w0 = (t0 >= 0) ? g_wt[t0] : 0.f;
        float w1v = (t1 >= 0) ? g_wt[t1] : 0.f;
#pragma unroll
        for (int ni = 0; ni < 8; ni++) {
            int col = n0 + wn * 64 + ni * 8 + tg * 2;
            float* c = acc[mi][ni];
            if (t0 >= 0)
                *(float2*)(g_y + (size_t)t0 * HD + col) =
                    make_float2(w0 * c[0], w0 * c[1]);
            if (t1 >= 0)
                *(float2*)(g_y + (size_t)t1 * HD + col) =
                    make_float2(w1v * c[2], w1v * c[3]);
        }
    }
}

// ---------------------------------------------------------------------------
// Kernel 4: combine the two expert contributions per token (full overwrite).
// ---------------------------------------------------------------------------
__global__ __launch_bounds__(256) void k_combine(float* __restrict__ out) {
    int i = blockIdx.x * 256 + threadIdx.x;
    int t = i >> 8;
    int c = i & 255;
    float4 a = ((const float4*)(g_y + (size_t)(2 * t) * HD))[c];
    float4 b = ((const float4*)(g_y + (size_t)(2 * t + 1) * HD))[c];
    ((float4*)out)[i] = make_float4(a.x + b.x, a.y + b.y, a.z + b.z, a.w + b.w);
}

// ---------------------------------------------------------------------------
// Launch
// ---------------------------------------------------------------------------
extern "C" void kernel_launch(void* const* d_in, const int* in_sizes, int n_in,
                              void* d_out, int out_size) {
    const float* hs = (const float*)d_in[0];
    const float* gw = (const float*)d_in[1];
    const float* w1 = (const float*)d_in[2];
    const float* w2 = (const float*)d_in[3];
    float* out = (float*)d_out;
    float* logits = (out_size >= TQ * HD + TQ * NE) ? out + (size_t)TQ * HD
                                                    : nullptr;

    static const int DSMEM = 98304;  // 3 stages x (16KB A + 16KB B)
    static bool attr_done = false;
    if (!attr_done) {
        cudaFuncSetAttribute(k_ffn1, cudaFuncAttributeMaxDynamicSharedMemorySize, DSMEM);
        cudaFuncSetAttribute(k_ffn2, cudaFuncAttributeMaxDynamicSharedMemorySize, DSMEM);
        attr_done = true;
    }

    float* w1t; cudaGetSymbolAddress((void**)&w1t, g_w1t);
    float* w2t; cudaGetSymbolAddress((void**)&w2t, g_w2t);
    float* hst; cudaGetSymbolAddress((void**)&hst, g_hst);

    k_zero<<<1, 32>>>();
    k_router<<<TQ / 8, 256>>>(hs, gw, logits);
    k_cvt<<<(NE * 2 * FD * HD / 4) / 256, 256>>>((const float4*)w1, (float4*)w1t,
                                                 NE * 2 * FD * HD / 4);
    k_cvt<<<(NE * HD * FD / 4) / 256, 256>>>((const float4*)w2, (float4*)w2t,
                                             NE * HD * FD / 4);
    k_cvt<<<(TQ * HD / 4) / 256, 256>>>((const float4*)hs, (float4*)hst,
                                        TQ * HD / 4);
    k_ffn1<<<dim3(FD / 64, NE * 32), 256, DSMEM>>>();
    k_ffn2<<<dim3(HD / 128, NE * 32), 256, DSMEM>>>();
    k_combine<<<(TQ * HD / 4) / 256, 256>>>(out);
}